// round 7
// baseline (speedup 1.0000x reference)
#include <cuda_runtime.h>
#include <cuda_bf16.h>
#include <cstdint>

#define N_NODES_MAX 100000
#define HID 64
#define E_MAX 1600000
#define SCAN_T 1024

// Scratch (device globals; no runtime allocation allowed)
__device__ __align__(16) float g_bufA[N_NODES_MAX * HID]; // layer feat
__device__ __align__(16) float g_bufB[N_NODES_MAX * HID]; // hs = (X@W)*dis
__device__ float g_dis[N_NODES_MAX];        // deg^{-1/2}
__device__ int   g_counts[N_NODES_MAX];     // in-degree (edges only)
__device__ int   g_cursor[N_NODES_MAX];
__device__ int   g_offsets[N_NODES_MAX + 1];
__device__ int   g_csr[E_MAX];              // src sorted by dst
__device__ int   g_is_i32;                  // dtype detection flag

// ---------------------------------------------------------------------------
// packed fp32 helpers (FFMA2)
// ---------------------------------------------------------------------------
__device__ __forceinline__ void fma2(unsigned long long& acc,
                                     unsigned long long x,
                                     unsigned long long w) {
    asm("fma.rn.f32x2 %0, %1, %2, %0;" : "+l"(acc) : "l"(x), "l"(w));
}

// edge accessors with dtype branch (flag: 1 => int32, 0 => int64)
__device__ __forceinline__ int edge_at(const void* ei, long long idx, int is32) {
    return is32 ? ((const int*)ei)[idx] : (int)((const long long*)ei)[idx];
}

// ---------------------------------------------------------------------------
// fused: zero counts/cursor everywhere; block 0 also detects edge dtype
// ---------------------------------------------------------------------------
__global__ void k_detect_zero(const unsigned long long* __restrict__ ei,
                              long long nwords, unsigned long long limit,
                              int* __restrict__ flag,
                              int* __restrict__ counts, int* __restrict__ cursor,
                              int N)
{
    int i = blockIdx.x * blockDim.x + threadIdx.x;
    if (i < N) { counts[i] = 0; cursor[i] = 0; }
    if (blockIdx.x == 0) {
        __shared__ int found;
        if (threadIdx.x == 0) found = 0;
        __syncthreads();
        for (long long t = threadIdx.x; t < nwords; t += blockDim.x) {
            if (ei[t] >= limit) { found = 1; break; }
        }
        __syncthreads();
        if (threadIdx.x == 0) *flag = found;  // 1 => int32, 0 => int64
    }
}

// count in-degrees straight from the raw edge buffer (dst half)
__global__ void k_count(const void* __restrict__ ei, int* __restrict__ counts,
                        long long E, const int* __restrict__ flag)
{
    long long e = (long long)blockIdx.x * blockDim.x + threadIdx.x;
    if (e >= E) return;
    int is32 = *flag;
    int dst = edge_at(ei, E + e, is32);
    atomicAdd(&counts[dst], 1);
}

// single-block exclusive scan of counts -> offsets; also dis = rsqrt(deg+1)
__global__ void __launch_bounds__(SCAN_T) k_scan(
    const int* __restrict__ counts, int* __restrict__ offsets,
    float* __restrict__ dis, int N)
{
    __shared__ int ssum[SCAN_T];
    const int tid = threadIdx.x;
    const int chunk = (N + SCAN_T - 1) / SCAN_T;
    const int lo = tid * chunk;
    const int hi = min(lo + chunk, N);
    int s = 0;
    for (int i = lo; i < hi; ++i) s += counts[i];
    ssum[tid] = s;
    __syncthreads();
    #pragma unroll
    for (int off = 1; off < SCAN_T; off <<= 1) {
        int t = (tid >= off) ? ssum[tid - off] : 0;
        __syncthreads();
        ssum[tid] += t;
        __syncthreads();
    }
    int run = ssum[tid] - s;
    for (int i = lo; i < hi; ++i) {
        int c = counts[i];
        offsets[i] = run;
        dis[i] = rsqrtf((float)(c + 1));
        run += c;
    }
    if (tid == SCAN_T - 1) offsets[N] = ssum[SCAN_T - 1];
}

// scatter src into CSR buckets, reading raw edges directly
__global__ void k_scatter(const void* __restrict__ ei,
                          const int* __restrict__ offsets,
                          int* __restrict__ cursor, int* __restrict__ csr,
                          long long E, const int* __restrict__ flag)
{
    long long e = (long long)blockIdx.x * blockDim.x + threadIdx.x;
    if (e >= E) return;
    int is32 = *flag;
    int src = edge_at(ei, e, is32);
    int dst = edge_at(ei, E + e, is32);
    int pos = offsets[dst] + atomicAdd(&cursor[dst], 1);
    csr[pos] = src;
}

// ---------------------------------------------------------------------------
// GEMM: hs = (X[N,K] @ W[K,64]) * dis[row]
// 256 threads/block, 128 rows x 64 cols per block, 4x8 per-thread tile,
// packed f32x2 accumulation (rows paired). W pre-duplicated in smem as f32x2.
// ---------------------------------------------------------------------------
template <int K>
__global__ void __launch_bounds__(256) k_gemm_scale(
    const float* __restrict__ X, const float* __restrict__ W,
    const float* __restrict__ dis, float* __restrict__ hs, int N)
{
    constexpr int KC = 32;                 // k-chunk
    constexpr int XSTR = 132;              // 132*4=528B row stride, 16B-aligned
    __shared__ __align__(16) float sX[KC * XSTR];               // sX[k][row]
    __shared__ __align__(16) unsigned long long sW2[KC * 64];   // dup pairs

    const int tid = threadIdx.x;
    const int r = tid >> 3;                // row group 0..31 (4 rows each)
    const int c = tid & 7;                 // col group 0..7  (8 cols each)
    const int row0 = blockIdx.x * 128;

    // accumulators: 2 row-pairs x 8 cols
    unsigned long long acc[2][8];
    #pragma unroll
    for (int i = 0; i < 2; ++i)
        #pragma unroll
        for (int j = 0; j < 8; ++j) acc[i][j] = 0ull;

    const float4* X4 = (const float4*)X;
    const float4* W4 = (const float4*)W;

    for (int kc0 = 0; kc0 < K; kc0 += KC) {
        // stage W chunk duplicated: 512 float4 reads, 256 threads -> 2 each
        #pragma unroll
        for (int i = 0; i < 2; ++i) {
            int idx = tid + i * 256;       // [0,512)
            int kk = idx >> 4;             // 0..31
            int cq = idx & 15;             // float4 col group
            float4 w = W4[(long long)(kc0 + kk) * 16 + cq];
            unsigned long long* dst = &sW2[kk * 64 + cq * 4];
            asm("mov.b64 %0, {%1, %1};" : "=l"(dst[0]) : "f"(w.x));
            asm("mov.b64 %0, {%1, %1};" : "=l"(dst[1]) : "f"(w.y));
            asm("mov.b64 %0, {%1, %1};" : "=l"(dst[2]) : "f"(w.z));
            asm("mov.b64 %0, {%1, %1};" : "=l"(dst[3]) : "f"(w.w));
        }
        // stage X chunk transposed: 128 rows x 8 float4 = 1024 loads, 4 iters
        #pragma unroll
        for (int i = 0; i < 4; ++i) {
            int idx = tid + i * 256;       // [0,1024)
            int row = idx >> 3;            // 0..127
            int kq = idx & 7;              // 0..7
            int grow = row0 + row;
            float4 v = make_float4(0.f, 0.f, 0.f, 0.f);
            if (grow < N) v = X4[(long long)grow * (K / 4) + (kc0 / 4) + kq];
            sX[(kq * 4 + 0) * XSTR + row] = v.x;
            sX[(kq * 4 + 1) * XSTR + row] = v.y;
            sX[(kq * 4 + 2) * XSTR + row] = v.z;
            sX[(kq * 4 + 3) * XSTR + row] = v.w;
        }
        __syncthreads();

        #pragma unroll
        for (int k = 0; k < KC; ++k) {
            // 4 rows as 2 packed pairs (16B-aligned LDS.128)
            float4 xv = *(const float4*)&sX[k * XSTR + r * 4];
            unsigned long long xp0 = *(unsigned long long*)&xv.x;
            unsigned long long xp1 = *(unsigned long long*)&xv.z;
            // 8 duplicated w pairs: 4 x LDS.128
            const unsigned long long* wp = &sW2[k * 64 + c * 8];
            #pragma unroll
            for (int j = 0; j < 8; ++j) {
                unsigned long long wd = wp[j];
                fma2(acc[0][j], xp0, wd);
                fma2(acc[1][j], xp1, wd);
            }
        }
        __syncthreads();
    }

    // epilogue: scale by dis[row], store hs rows
    #pragma unroll
    for (int rp = 0; rp < 2; ++rp) {
        #pragma unroll
        for (int half = 0; half < 2; ++half) {
            int row = row0 + r * 4 + rp * 2 + half;
            if (row < N) {
                float d = dis[row];
                float4 o0, o1;
                float* f;
                f = (float*)&acc[rp][0]; o0.x = f[half] * d;
                f = (float*)&acc[rp][1]; o0.y = f[half] * d;
                f = (float*)&acc[rp][2]; o0.z = f[half] * d;
                f = (float*)&acc[rp][3]; o0.w = f[half] * d;
                f = (float*)&acc[rp][4]; o1.x = f[half] * d;
                f = (float*)&acc[rp][5]; o1.y = f[half] * d;
                f = (float*)&acc[rp][6]; o1.z = f[half] * d;
                f = (float*)&acc[rp][7]; o1.w = f[half] * d;
                float4* dst = (float4*)&hs[(long long)row * 64 + c * 8];
                dst[0] = o0;
                dst[1] = o1;
            }
        }
    }
}

// ---------------------------------------------------------------------------
// Fused aggregation + finalize (+ optional readout).
// Half-warp (16 lanes) per node; one LDG.128 per neighbor per half-warp.
// 8 neighbors in flight for MLP.
// ---------------------------------------------------------------------------
template <bool READOUT>
__global__ void __launch_bounds__(256) k_agg(
    const float4* __restrict__ hs, const int* __restrict__ offsets,
    const int* __restrict__ csr, const float* __restrict__ dis,
    const float* __restrict__ b, float* __restrict__ out,
    const float* __restrict__ Wout, const float* __restrict__ bout, int N)
{
    int node = blockIdx.x * 16 + (threadIdx.x >> 4);
    int h = threadIdx.x & 15;
    if (node >= N) return;

    float4 a = hs[(long long)node * 16 + h];  // self loop

    int beg = offsets[node];
    int end = offsets[node + 1];
    int p = beg;
    for (; p + 7 < end; p += 8) {
        int s[8];
        #pragma unroll
        for (int i = 0; i < 8; ++i) s[i] = csr[p + i];
        float4 v[8];
        #pragma unroll
        for (int i = 0; i < 8; ++i) v[i] = __ldg(&hs[(long long)s[i] * 16 + h]);
        float4 t0, t1;
        t0.x = (v[0].x + v[1].x) + (v[2].x + v[3].x);
        t0.y = (v[0].y + v[1].y) + (v[2].y + v[3].y);
        t0.z = (v[0].z + v[1].z) + (v[2].z + v[3].z);
        t0.w = (v[0].w + v[1].w) + (v[2].w + v[3].w);
        t1.x = (v[4].x + v[5].x) + (v[6].x + v[7].x);
        t1.y = (v[4].y + v[5].y) + (v[6].y + v[7].y);
        t1.z = (v[4].z + v[5].z) + (v[6].z + v[7].z);
        t1.w = (v[4].w + v[5].w) + (v[6].w + v[7].w);
        a.x += t0.x + t1.x;
        a.y += t0.y + t1.y;
        a.z += t0.z + t1.z;
        a.w += t0.w + t1.w;
    }
    for (; p + 3 < end; p += 4) {
        int s0 = csr[p], s1 = csr[p + 1], s2 = csr[p + 2], s3 = csr[p + 3];
        float4 v0 = __ldg(&hs[(long long)s0 * 16 + h]);
        float4 v1 = __ldg(&hs[(long long)s1 * 16 + h]);
        float4 v2 = __ldg(&hs[(long long)s2 * 16 + h]);
        float4 v3 = __ldg(&hs[(long long)s3 * 16 + h]);
        a.x += (v0.x + v1.x) + (v2.x + v3.x);
        a.y += (v0.y + v1.y) + (v2.y + v3.y);
        a.z += (v0.z + v1.z) + (v2.z + v3.z);
        a.w += (v0.w + v1.w) + (v2.w + v3.w);
    }
    for (; p < end; ++p) {
        int s0 = csr[p];
        float4 v0 = __ldg(&hs[(long long)s0 * 16 + h]);
        a.x += v0.x; a.y += v0.y; a.z += v0.z; a.w += v0.w;
    }

    float d = dis[node];
    float4 bb = ((const float4*)b)[h];
    float4 f;
    f.x = fmaxf(fmaf(d, a.x, bb.x), 0.f);
    f.y = fmaxf(fmaf(d, a.y, bb.y), 0.f);
    f.z = fmaxf(fmaf(d, a.z, bb.z), 0.f);
    f.w = fmaxf(fmaf(d, a.w, bb.w), 0.f);

    if (READOUT) {
        float4 w = ((const float4*)Wout)[h];
        float s = f.x * w.x + f.y * w.y + f.z * w.z + f.w * w.w;
        #pragma unroll
        for (int o = 8; o; o >>= 1) s += __shfl_xor_sync(0xFFFFFFFFu, s, o);
        if (h == 0) out[node] = s + bout[0];
    } else {
        ((float4*)out)[(long long)node * 16 + h] = f;
    }
}

// ---------------------------------------------------------------------------
extern "C" void kernel_launch(void* const* d_in, const int* in_sizes, int n_in,
                              void* d_out, int out_size)
{
    const float* x    = (const float*)d_in[0];
    const void*  eraw = d_in[1];
    const float* W1   = (const float*)d_in[2];
    const float* b1   = (const float*)d_in[3];
    const float* W2   = (const float*)d_in[4];
    const float* b2   = (const float*)d_in[5];
    const float* W3   = (const float*)d_in[6];
    const float* b3   = (const float*)d_in[7];
    const float* Wout = (const float*)d_in[8];
    const float* bout = (const float*)d_in[9];
    float*       out  = (float*)d_out;

    const int N = in_sizes[0] / 128;
    const long long E = in_sizes[1] / 2;

    float *bufA, *bufB, *dis;
    int *flag, *counts, *cursor, *offsets, *csr;
    cudaGetSymbolAddress((void**)&bufA,    g_bufA);
    cudaGetSymbolAddress((void**)&bufB,    g_bufB);
    cudaGetSymbolAddress((void**)&dis,     g_dis);
    cudaGetSymbolAddress((void**)&flag,    g_is_i32);
    cudaGetSymbolAddress((void**)&counts,  g_counts);
    cudaGetSymbolAddress((void**)&cursor,  g_cursor);
    cudaGetSymbolAddress((void**)&offsets, g_offsets);
    cudaGetSymbolAddress((void**)&csr,     g_csr);

    const int TB = 256;
    long long nwords = E < 4096 ? E : 4096;

    const int gemm_blocks = (N + 127) / 128;
    const int agg_blocks  = (N + 15) / 16;
    const int edge_blocks = (int)((E + TB - 1) / TB);

    // 0: zero + dtype detect
    k_detect_zero<<<(N + TB - 1) / TB, TB>>>(
        (const unsigned long long*)eraw, nwords, (unsigned long long)N,
        flag, counts, cursor, N);
    // 1: in-degree count (raw edges)
    k_count<<<edge_blocks, TB>>>(eraw, counts, E, flag);
    // 2: scan -> offsets, dis
    k_scan<<<1, SCAN_T>>>(counts, offsets, dis, N);
    // 3: GEMM layer 1 (only needs dis) — lands in the profiler window
    k_gemm_scale<128><<<gemm_blocks, 256>>>(x, W1, dis, bufB, N);
    // 4: scatter -> CSR (raw edges)
    k_scatter<<<edge_blocks, TB>>>(eraw, offsets, cursor, csr, E, flag);
    // 5: agg layer 1
    k_agg<false><<<agg_blocks, TB>>>((const float4*)bufB, offsets, csr, dis, b1,
                                     bufA, nullptr, nullptr, N);
    // Layer 2 (K=64)
    k_gemm_scale<64><<<gemm_blocks, 256>>>(bufA, W2, dis, bufB, N);
    k_agg<false><<<agg_blocks, TB>>>((const float4*)bufB, offsets, csr, dis, b2,
                                     bufA, nullptr, nullptr, N);
    // Layer 3 (K=64) + fused readout
    k_gemm_scale<64><<<gemm_blocks, 256>>>(bufA, W3, dis, bufB, N);
    k_agg<true><<<agg_blocks, TB>>>((const float4*)bufB, offsets, csr, dis, b3,
                                    out, Wout, bout, N);
}

// round 8
// speedup vs baseline: 1.9170x; 1.9170x over previous
#include <cuda_runtime.h>
#include <cuda_bf16.h>
#include <cstdint>

#define N_NODES_MAX 100000
#define HID 64
#define E_MAX 1600000
#define SCAN_T 1024

// Scratch (device globals; no runtime allocation allowed)
__device__ __align__(16) float g_bufA[N_NODES_MAX * HID]; // layer feat
__device__ __align__(16) float g_bufB[N_NODES_MAX * HID]; // hs = (X@W)*dis
__device__ float g_dis[N_NODES_MAX];        // deg^{-1/2}
__device__ int   g_counts[N_NODES_MAX];     // in-degree (edges only)
__device__ int   g_cursor[N_NODES_MAX];
__device__ int   g_offsets[N_NODES_MAX + 1];
__device__ int   g_csr[E_MAX];              // src sorted by dst
__device__ int   g_is_i32;                  // dtype detection flag

// ---------------------------------------------------------------------------
// packed fp32 helpers (FFMA2)
// ---------------------------------------------------------------------------
__device__ __forceinline__ void fma2(unsigned long long& acc,
                                     unsigned long long x,
                                     unsigned long long w) {
    asm("fma.rn.f32x2 %0, %1, %2, %0;" : "+l"(acc) : "l"(x), "l"(w));
}

// edge accessors with dtype branch (flag: 1 => int32, 0 => int64)
__device__ __forceinline__ int edge_at(const void* ei, long long idx, int is32) {
    return is32 ? ((const int*)ei)[idx] : (int)((const long long*)ei)[idx];
}

// ---------------------------------------------------------------------------
// fused: zero counts/cursor everywhere; block 0 also detects edge dtype
// ---------------------------------------------------------------------------
__global__ void k_detect_zero(const unsigned long long* __restrict__ ei,
                              long long nwords, unsigned long long limit,
                              int* __restrict__ flag,
                              int* __restrict__ counts, int* __restrict__ cursor,
                              int N)
{
    int i = blockIdx.x * blockDim.x + threadIdx.x;
    if (i < N) { counts[i] = 0; cursor[i] = 0; }
    if (blockIdx.x == 0) {
        __shared__ int found;
        if (threadIdx.x == 0) found = 0;
        __syncthreads();
        for (long long t = threadIdx.x; t < nwords; t += blockDim.x) {
            if (ei[t] >= limit) { found = 1; break; }
        }
        __syncthreads();
        if (threadIdx.x == 0) *flag = found;  // 1 => int32, 0 => int64
    }
}

// count in-degrees straight from the raw edge buffer (dst half)
__global__ void k_count(const void* __restrict__ ei, int* __restrict__ counts,
                        long long E, const int* __restrict__ flag)
{
    long long e = (long long)blockIdx.x * blockDim.x + threadIdx.x;
    if (e >= E) return;
    int is32 = *flag;
    int dst = edge_at(ei, E + e, is32);
    atomicAdd(&counts[dst], 1);
}

// single-block exclusive scan of counts -> offsets; also dis = rsqrt(deg+1)
__global__ void __launch_bounds__(SCAN_T) k_scan(
    const int* __restrict__ counts, int* __restrict__ offsets,
    float* __restrict__ dis, int N)
{
    __shared__ int ssum[SCAN_T];
    const int tid = threadIdx.x;
    const int chunk = (N + SCAN_T - 1) / SCAN_T;
    const int lo = tid * chunk;
    const int hi = min(lo + chunk, N);
    int s = 0;
    for (int i = lo; i < hi; ++i) s += counts[i];
    ssum[tid] = s;
    __syncthreads();
    #pragma unroll
    for (int off = 1; off < SCAN_T; off <<= 1) {
        int t = (tid >= off) ? ssum[tid - off] : 0;
        __syncthreads();
        ssum[tid] += t;
        __syncthreads();
    }
    int run = ssum[tid] - s;
    for (int i = lo; i < hi; ++i) {
        int c = counts[i];
        offsets[i] = run;
        dis[i] = rsqrtf((float)(c + 1));
        run += c;
    }
    if (tid == SCAN_T - 1) offsets[N] = ssum[SCAN_T - 1];
}

// scatter src into CSR buckets, reading raw edges directly
__global__ void k_scatter(const void* __restrict__ ei,
                          const int* __restrict__ offsets,
                          int* __restrict__ cursor, int* __restrict__ csr,
                          long long E, const int* __restrict__ flag)
{
    long long e = (long long)blockIdx.x * blockDim.x + threadIdx.x;
    if (e >= E) return;
    int is32 = *flag;
    int src = edge_at(ei, e, is32);
    int dst = edge_at(ei, E + e, is32);
    int pos = offsets[dst] + atomicAdd(&cursor[dst], 1);
    csr[pos] = src;
}

// ---------------------------------------------------------------------------
// GEMM: hs = (X[N,K] @ W[K,64]) * dis[row]
// (reverted to the measured-good R6 version: 128 threads/block, 128x64 tile,
// 8x8 per-thread, f32x2 accumulation, conflict-free smem layout)
// ---------------------------------------------------------------------------
template <int K>
__global__ void __launch_bounds__(128) k_gemm_scale(
    const float* __restrict__ X, const float* __restrict__ W,
    const float* __restrict__ dis, float* __restrict__ hs, int N)
{
    constexpr int KC = 32;                 // k-chunk
    constexpr int XSTR = 132;              // 132*4=528B row stride, 16B-aligned
    __shared__ __align__(16) float sX[KC * XSTR];  // sX[k][row]
    __shared__ __align__(16) float sW[KC * 64];    // sW[k][col]

    const int tid = threadIdx.x;
    const int r = tid >> 3;                // row group 0..15 (8 rows each)
    const int c = tid & 7;                 // col group 0..7  (8 cols each)
    const int row0 = blockIdx.x * 128;

    unsigned long long acc[4][8];
    #pragma unroll
    for (int i = 0; i < 4; ++i)
        #pragma unroll
        for (int j = 0; j < 8; ++j) acc[i][j] = 0ull;

    const float4* X4 = (const float4*)X;
    const float4* W4 = (const float4*)W;

    for (int kc0 = 0; kc0 < K; kc0 += KC) {
        #pragma unroll
        for (int i = 0; i < 4; ++i) {
            int idx = tid + i * 128;       // [0,512)
            int kk = idx >> 4;
            int cq = idx & 15;
            float4 w = W4[(long long)(kc0 + kk) * 16 + cq];
            *(float4*)&sW[kk * 64 + cq * 4] = w;
        }
        #pragma unroll
        for (int i = 0; i < 8; ++i) {
            int idx = tid + i * 128;       // [0,1024)
            int row = idx >> 3;
            int kq = idx & 7;
            int grow = row0 + row;
            float4 v = make_float4(0.f, 0.f, 0.f, 0.f);
            if (grow < N) v = X4[(long long)grow * (K / 4) + (kc0 / 4) + kq];
            sX[(kq * 4 + 0) * XSTR + row] = v.x;
            sX[(kq * 4 + 1) * XSTR + row] = v.y;
            sX[(kq * 4 + 2) * XSTR + row] = v.z;
            sX[(kq * 4 + 3) * XSTR + row] = v.w;
        }
        __syncthreads();

        #pragma unroll
        for (int k = 0; k < KC; ++k) {
            float4 xa = *(const float4*)&sX[k * XSTR + r * 8 + 0];
            float4 xb = *(const float4*)&sX[k * XSTR + r * 8 + 4];
            float4 wa = *(const float4*)&sW[k * 64 + c * 8 + 0];
            float4 wb = *(const float4*)&sW[k * 64 + c * 8 + 4];
            unsigned long long xp[4];
            xp[0] = *(unsigned long long*)&xa.x;
            xp[1] = *(unsigned long long*)&xa.z;
            xp[2] = *(unsigned long long*)&xb.x;
            xp[3] = *(unsigned long long*)&xb.z;
            float wv[8] = {wa.x, wa.y, wa.z, wa.w, wb.x, wb.y, wb.z, wb.w};
            #pragma unroll
            for (int j = 0; j < 8; ++j) {
                unsigned long long wd;
                asm("mov.b64 %0, {%1, %1};" : "=l"(wd) : "f"(wv[j]));
                #pragma unroll
                for (int rp = 0; rp < 4; ++rp) fma2(acc[rp][j], xp[rp], wd);
            }
        }
        __syncthreads();
    }

    #pragma unroll
    for (int rp = 0; rp < 4; ++rp) {
        #pragma unroll
        for (int half = 0; half < 2; ++half) {
            int row = row0 + r * 8 + rp * 2 + half;
            if (row < N) {
                float d = dis[row];
                float4 o0, o1;
                float* f;
                f = (float*)&acc[rp][0]; o0.x = f[half] * d;
                f = (float*)&acc[rp][1]; o0.y = f[half] * d;
                f = (float*)&acc[rp][2]; o0.z = f[half] * d;
                f = (float*)&acc[rp][3]; o0.w = f[half] * d;
                f = (float*)&acc[rp][4]; o1.x = f[half] * d;
                f = (float*)&acc[rp][5]; o1.y = f[half] * d;
                f = (float*)&acc[rp][6]; o1.z = f[half] * d;
                f = (float*)&acc[rp][7]; o1.w = f[half] * d;
                float4* dst = (float4*)&hs[(long long)row * 64 + c * 8];
                dst[0] = o0;
                dst[1] = o1;
            }
        }
    }
}

// ---------------------------------------------------------------------------
// Fused aggregation + finalize (+ optional readout).
// Half-warp (16 lanes) per node; one LDG.128 per neighbor per half-warp.
// 8 neighbors in flight for MLP.
// ---------------------------------------------------------------------------
template <bool READOUT>
__global__ void __launch_bounds__(256) k_agg(
    const float4* __restrict__ hs, const int* __restrict__ offsets,
    const int* __restrict__ csr, const float* __restrict__ dis,
    const float* __restrict__ b, float* __restrict__ out,
    const float* __restrict__ Wout, const float* __restrict__ bout, int N)
{
    int node = blockIdx.x * 16 + (threadIdx.x >> 4);
    int h = threadIdx.x & 15;
    if (node >= N) return;

    float4 a = hs[(long long)node * 16 + h];  // self loop

    int beg = offsets[node];
    int end = offsets[node + 1];
    int p = beg;
    for (; p + 7 < end; p += 8) {
        int s[8];
        #pragma unroll
        for (int i = 0; i < 8; ++i) s[i] = csr[p + i];
        float4 v[8];
        #pragma unroll
        for (int i = 0; i < 8; ++i) v[i] = __ldg(&hs[(long long)s[i] * 16 + h]);
        float4 t0, t1;
        t0.x = (v[0].x + v[1].x) + (v[2].x + v[3].x);
        t0.y = (v[0].y + v[1].y) + (v[2].y + v[3].y);
        t0.z = (v[0].z + v[1].z) + (v[2].z + v[3].z);
        t0.w = (v[0].w + v[1].w) + (v[2].w + v[3].w);
        t1.x = (v[4].x + v[5].x) + (v[6].x + v[7].x);
        t1.y = (v[4].y + v[5].y) + (v[6].y + v[7].y);
        t1.z = (v[4].z + v[5].z) + (v[6].z + v[7].z);
        t1.w = (v[4].w + v[5].w) + (v[6].w + v[7].w);
        a.x += t0.x + t1.x;
        a.y += t0.y + t1.y;
        a.z += t0.z + t1.z;
        a.w += t0.w + t1.w;
    }
    for (; p + 3 < end; p += 4) {
        int s0 = csr[p], s1 = csr[p + 1], s2 = csr[p + 2], s3 = csr[p + 3];
        float4 v0 = __ldg(&hs[(long long)s0 * 16 + h]);
        float4 v1 = __ldg(&hs[(long long)s1 * 16 + h]);
        float4 v2 = __ldg(&hs[(long long)s2 * 16 + h]);
        float4 v3 = __ldg(&hs[(long long)s3 * 16 + h]);
        a.x += (v0.x + v1.x) + (v2.x + v3.x);
        a.y += (v0.y + v1.y) + (v2.y + v3.y);
        a.z += (v0.z + v1.z) + (v2.z + v3.z);
        a.w += (v0.w + v1.w) + (v2.w + v3.w);
    }
    for (; p < end; ++p) {
        int s0 = csr[p];
        float4 v0 = __ldg(&hs[(long long)s0 * 16 + h]);
        a.x += v0.x; a.y += v0.y; a.z += v0.z; a.w += v0.w;
    }

    float d = dis[node];
    float4 bb = ((const float4*)b)[h];
    float4 f;
    f.x = fmaxf(fmaf(d, a.x, bb.x), 0.f);
    f.y = fmaxf(fmaf(d, a.y, bb.y), 0.f);
    f.z = fmaxf(fmaf(d, a.z, bb.z), 0.f);
    f.w = fmaxf(fmaf(d, a.w, bb.w), 0.f);

    if (READOUT) {
        float4 w = ((const float4*)Wout)[h];
        float s = f.x * w.x + f.y * w.y + f.z * w.z + f.w * w.w;
        #pragma unroll
        for (int o = 8; o; o >>= 1) s += __shfl_xor_sync(0xFFFFFFFFu, s, o);
        if (h == 0) out[node] = s + bout[0];
    } else {
        ((float4*)out)[(long long)node * 16 + h] = f;
    }
}

// ---------------------------------------------------------------------------
extern "C" void kernel_launch(void* const* d_in, const int* in_sizes, int n_in,
                              void* d_out, int out_size)
{
    const float* x    = (const float*)d_in[0];
    const void*  eraw = d_in[1];
    const float* W1   = (const float*)d_in[2];
    const float* b1   = (const float*)d_in[3];
    const float* W2   = (const float*)d_in[4];
    const float* b2   = (const float*)d_in[5];
    const float* W3   = (const float*)d_in[6];
    const float* b3   = (const float*)d_in[7];
    const float* Wout = (const float*)d_in[8];
    const float* bout = (const float*)d_in[9];
    float*       out  = (float*)d_out;

    const int N = in_sizes[0] / 128;
    const long long E = in_sizes[1] / 2;

    float *bufA, *bufB, *dis;
    int *flag, *counts, *cursor, *offsets, *csr;
    cudaGetSymbolAddress((void**)&bufA,    g_bufA);
    cudaGetSymbolAddress((void**)&bufB,    g_bufB);
    cudaGetSymbolAddress((void**)&dis,     g_dis);
    cudaGetSymbolAddress((void**)&flag,    g_is_i32);
    cudaGetSymbolAddress((void**)&counts,  g_counts);
    cudaGetSymbolAddress((void**)&cursor,  g_cursor);
    cudaGetSymbolAddress((void**)&offsets, g_offsets);
    cudaGetSymbolAddress((void**)&csr,     g_csr);

    const int TB = 256;
    long long nwords = E < 4096 ? E : 4096;

    const int gemm_blocks = (N + 127) / 128;
    const int agg_blocks  = (N + 15) / 16;
    const int edge_blocks = (int)((E + TB - 1) / TB);

    // 0: zero + dtype detect
    k_detect_zero<<<(N + TB - 1) / TB, TB>>>(
        (const unsigned long long*)eraw, nwords, (unsigned long long)N,
        flag, counts, cursor, N);
    // 1: in-degree count (raw edges)
    k_count<<<edge_blocks, TB>>>(eraw, counts, E, flag);
    // 2: scan -> offsets, dis
    k_scan<<<1, SCAN_T>>>(counts, offsets, dis, N);
    // 3: GEMM layer 1 — profiled launch, must confirm ~52us again
    k_gemm_scale<128><<<gemm_blocks, 128>>>(x, W1, dis, bufB, N);
    // 4: scatter -> CSR (raw edges)
    k_scatter<<<edge_blocks, TB>>>(eraw, offsets, cursor, csr, E, flag);
    // 5: agg layer 1
    k_agg<false><<<agg_blocks, TB>>>((const float4*)bufB, offsets, csr, dis, b1,
                                     bufA, nullptr, nullptr, N);
    // Layer 2 (K=64)
    k_gemm_scale<64><<<gemm_blocks, 128>>>(bufA, W2, dis, bufB, N);
    k_agg<false><<<agg_blocks, TB>>>((const float4*)bufB, offsets, csr, dis, b2,
                                     bufA, nullptr, nullptr, N);
    // Layer 3 (K=64) + fused readout
    k_gemm_scale<64><<<gemm_blocks, 128>>>(bufA, W3, dis, bufB, N);
    k_agg<true><<<agg_blocks, TB>>>((const float4*)bufB, offsets, csr, dis, b3,
                                    out, Wout, bout, N);
}